// round 8
// baseline (speedup 1.0000x reference)
#include <cuda_runtime.h>
#include <cuda_fp16.h>
#include <cstdint>
#include <math.h>

#define NN 50000
#define TT 4
#define FF 128
#define EE 800000
#define SCAN_B 256
#define NB ((NN + SCAN_B - 1) / SCAN_B)   // 196

// ---------------- scratch (static device globals; no allocation) ----------------
__device__ int    g_deg[NN];
__device__ float  g_dinv[NN];
__device__ int    g_cnt[NN];
__device__ int    g_bsum[NB];
__device__ int    g_cursor[NN];
__device__ int    g_rowoff4[(size_t)TT * (NN + 1)];
__device__ int    g_col4[(size_t)TT * EE];
__device__ float  g_w4[(size_t)TT * EE];
__device__ __half g_xh[(size_t)TT * NN * FF];
__device__ __half g_Tx1h[(size_t)NN * FF];
__device__ __half g_Tx2h[(size_t)NN * FF];
__device__ float  g_H[(size_t)NN * FF];
__device__ __half g_Hh[(size_t)NN * FF];
__device__ __half g_HRh[(size_t)NN * FF];
__device__ __half g_D1h[(size_t)NN * FF];
__device__ float  g_Gx[(size_t)NN * 384];
__device__ float  g_Z[(size_t)NN * FF];
__device__ __half g_WxHi[384 * 384],  g_WxLo[384 * 384];    // [No][K]
__device__ __half g_WhHi[256 * 384],  g_WhLo[256 * 384];
__device__ __half g_WhhHi[128 * 384], g_WhhLo[128 * 384];
__device__ __half g_Wd1Hi[128 * 128], g_Wd1Lo[128 * 128];
__device__ __half g_Wd2Hi[128 * 128], g_Wd2Lo[128 * 128];
__device__ float  g_bx[384];
__device__ float  g_bh[256];

// ---------------- helpers ----------------
__device__ __forceinline__ uint32_t smem_u32(const void* p) {
    uint32_t a;
    asm("{ .reg .u64 t; cvta.to.shared.u64 t, %1; cvt.u32.u64 %0, t; }" : "=r"(a) : "l"(p));
    return a;
}
__device__ __forceinline__ void ldm_x4(uint32_t& r0, uint32_t& r1, uint32_t& r2, uint32_t& r3,
                                       uint32_t addr) {
    asm volatile("ldmatrix.sync.aligned.m8n8.x4.shared.b16 {%0,%1,%2,%3}, [%4];"
                 : "=r"(r0), "=r"(r1), "=r"(r2), "=r"(r3) : "r"(addr));
}
__device__ __forceinline__ void mma_f16(float* d, const uint32_t* a, const uint32_t* b) {
    asm volatile(
        "mma.sync.aligned.m16n8k16.row.col.f32.f16.f16.f32 "
        "{%0,%1,%2,%3}, {%4,%5,%6,%7}, {%8,%9}, {%0,%1,%2,%3};"
        : "+f"(d[0]), "+f"(d[1]), "+f"(d[2]), "+f"(d[3])
        : "r"(a[0]), "r"(a[1]), "r"(a[2]), "r"(a[3]), "r"(b[0]), "r"(b[1]));
}

// ---------------- graph preprocessing (edge_index is int32) ----------------
__global__ void k_hist(const int* __restrict__ src, const int* __restrict__ dst,
                       int* __restrict__ deg, int* __restrict__ cnt, int E) {
    int i = blockIdx.x * blockDim.x + threadIdx.x;
    if (i < E) {
        unsigned s = (unsigned)src[i];
        unsigned d = (unsigned)dst[i];
        if (s < NN) atomicAdd(&deg[s], 1);
        if (d < NN) atomicAdd(&cnt[d], 1);
    }
}
__global__ void k_dinv(const int* __restrict__ deg, float* __restrict__ dinv, int n) {
    int i = blockIdx.x * blockDim.x + threadIdx.x;
    if (i < n) { int d = deg[i]; dinv[i] = d > 0 ? rsqrtf((float)d) : 0.0f; }
}
__global__ void k_scan_part(const int* __restrict__ cnt, int* __restrict__ bsum, int n) {
    __shared__ int s[SCAN_B];
    int tid = threadIdx.x;
    int idx = blockIdx.x * SCAN_B + tid;
    s[tid] = (idx < n) ? cnt[idx] : 0;
    __syncthreads();
#pragma unroll
    for (int off = SCAN_B / 2; off > 0; off >>= 1) {
        if (tid < off) s[tid] += s[tid + off];
        __syncthreads();
    }
    if (tid == 0) bsum[blockIdx.x] = s[0];
}
__global__ void k_scan_top(int* __restrict__ bsum, int nb, int* __restrict__ rowoff, int n) {
    __shared__ int s[SCAN_B];
    int tid = threadIdx.x;
    int v = (tid < nb) ? bsum[tid] : 0;
    s[tid] = v;
    __syncthreads();
#pragma unroll
    for (int off = 1; off < SCAN_B; off <<= 1) {
        int t = (tid >= off) ? s[tid - off] : 0;
        __syncthreads();
        s[tid] += t;
        __syncthreads();
    }
    if (tid < nb) bsum[tid] = s[tid] - v;
    if (tid == SCAN_B - 1) rowoff[n] = s[SCAN_B - 1];
}
__global__ void k_scan_down(const int* __restrict__ cnt, const int* __restrict__ bsum,
                            int* __restrict__ rowoff, int n) {
    __shared__ int s[SCAN_B];
    int tid = threadIdx.x;
    int idx = blockIdx.x * SCAN_B + tid;
    int v = (idx < n) ? cnt[idx] : 0;
    s[tid] = v;
    __syncthreads();
#pragma unroll
    for (int off = 1; off < SCAN_B; off <<= 1) {
        int t = (tid >= off) ? s[tid - off] : 0;
        __syncthreads();
        s[tid] += t;
        __syncthreads();
    }
    if (idx < n) rowoff[idx] = bsum[blockIdx.x] + s[tid] - v;
}
__global__ void k_scatter(const int* __restrict__ src, const int* __restrict__ dst,
                          const float* __restrict__ dinv, int* __restrict__ cursor,
                          int* __restrict__ col, float* __restrict__ w, int E) {
    int i = blockIdx.x * blockDim.x + threadIdx.x;
    if (i < E) {
        unsigned s = (unsigned)src[i], d = (unsigned)dst[i];
        if (s < NN && d < NN) {
            int pos = atomicAdd(&cursor[d], 1);
            col[pos] = (int)s;
            w[pos] = -dinv[s] * dinv[d];
        }
    }
}

// ---------------- fp32 -> fp16 cast ----------------
__global__ void k_cast(const float4* __restrict__ X, __half2* __restrict__ Y, int n4) {
    int i = blockIdx.x * blockDim.x + threadIdx.x;
    if (i < n4) {
        float4 v = X[i];
        Y[2 * i]     = __floats2half2_rn(v.x, v.y);
        Y[2 * i + 1] = __floats2half2_rn(v.z, v.w);
    }
}

// ---------------- SpMM fp16 ----------------
__global__ void k_spmm_h(const int* __restrict__ rowoff, const int* __restrict__ col,
                         const float* __restrict__ w, const __half2* __restrict__ X,
                         const __half2* __restrict__ base, __half2* __restrict__ Y, int n) {
    int r = blockIdx.x * 4 + threadIdx.y;
    if (r >= n) return;
    int f = threadIdx.x;  // 0..63
    int e0 = rowoff[r], e1 = rowoff[r + 1];
    float ax = 0.f, ay = 0.f;
    int e = e0;
    for (; e + 4 <= e1; e += 4) {
        int c0 = col[e], c1 = col[e + 1], c2 = col[e + 2], c3 = col[e + 3];
        float w0 = w[e], w1 = w[e + 1], w2 = w[e + 2], w3 = w[e + 3];
        float2 v0 = __half22float2(X[(size_t)c0 * 64 + f]);
        float2 v1 = __half22float2(X[(size_t)c1 * 64 + f]);
        float2 v2 = __half22float2(X[(size_t)c2 * 64 + f]);
        float2 v3 = __half22float2(X[(size_t)c3 * 64 + f]);
        ax += w0 * v0.x + w1 * v1.x + w2 * v2.x + w3 * v3.x;
        ay += w0 * v0.y + w1 * v1.y + w2 * v2.y + w3 * v3.y;
    }
    for (; e < e1; e++) {
        float2 v = __half22float2(X[(size_t)col[e] * 64 + f]);
        float ww = w[e];
        ax += ww * v.x;
        ay += ww * v.y;
    }
    size_t o = (size_t)r * 64 + f;
    if (base) {
        float2 b = __half22float2(base[o]);
        ax = 2.f * ax - b.x;
        ay = 2.f * ay - b.y;
    }
    Y[o] = __floats2half2_rn(ax, ay);
}

// ---------------- fp16 MMA GEMM with fused gate epilogues ----------------
// mode 0: plain -> C (fp32) and/or Ch (fp16), optional relu
// mode 1: Gh GEMM. n0==0 cols: Z = sigmoid(Gx[:,0:128]+acc+bias)
//                  n0==128 cols: HRh = fp16(H * sigmoid(Gx[:,128:256]+acc+bias))
// mode 2: Whh GEMM. ht = tanh(Gx[:,256:384]+acc+bias); h = Z*H+(1-Z)*ht -> H, Hh
#define LDS_H 40
#define TILE_B (128 * LDS_H * 2)
#define STAGE_B (3 * TILE_B)
#define GEMM_SMEM_BYTES (1024 + 2 * STAGE_B)
__global__ void __launch_bounds__(256) k_gemm_h(
    const __half* __restrict__ A0, const __half* __restrict__ A1, const __half* __restrict__ A2,
    int kblocks, const __half* __restrict__ Bhi, const __half* __restrict__ Blo, int ldb,
    const float* __restrict__ bias, int mode, int act,
    float* __restrict__ C, __half* __restrict__ Ch,
    const float* __restrict__ Gx, float* __restrict__ H, float* __restrict__ Z,
    __half* __restrict__ HRh, __half* __restrict__ Hh,
    int n, int No) {
    extern __shared__ char smem[];
    float* bias_s = (float*)smem;
    uint32_t sb = smem_u32(smem);

    const int tid = threadIdx.x;
    const int lane = tid & 31, wid = tid >> 5;
    const int wm = wid & 1, wn = wid >> 1;
    const int m0 = blockIdx.x * 128, n0 = blockIdx.y * 128;

    if (tid < 128) bias_s[tid] = bias[n0 + tid];

    const __half* Ap[3] = {A0, A1, A2};
    const int nch = kblocks * 4;

    const int ldr = tid >> 1;
    const int ldk = (tid & 1) * 16;
    const int garow = m0 + ldr;
    const bool aval = garow < n;
    const __half* gbh_row = Bhi + (size_t)(n0 + ldr) * ldb + ldk;
    const __half* gbl_row = Blo + (size_t)(n0 + ldr) * ldb + ldk;

    const uint32_t OFF_ST[2] = {1024u, 1024u + STAGE_B};
    const uint32_t OA = 0, OBH = TILE_B, OBL = 2 * TILE_B;

    const int a_row = wm * 64 + (lane & 15);
    const int a_koff = (lane >> 4) * 8;
    const int b_row = wn * 32 + (lane >> 4) * 8 + (lane & 7);
    const int b_koff = ((lane >> 3) & 1) * 8;

    float acc[4][4][4];
#pragma unroll
    for (int i = 0; i < 4; i++)
#pragma unroll
        for (int j = 0; j < 4; j++)
#pragma unroll
            for (int q = 0; q < 4; q++) acc[i][j][q] = 0.f;

    uint4 av[2], bhv[2], blv[2];
    {
        const __half* ga = Ap[0] + (size_t)garow * 128 + ldk;
        av[0] = aval ? *(const uint4*)ga : make_uint4(0, 0, 0, 0);
        av[1] = aval ? *(const uint4*)(ga + 8) : make_uint4(0, 0, 0, 0);
        bhv[0] = *(const uint4*)gbh_row;
        bhv[1] = *(const uint4*)(gbh_row + 8);
        blv[0] = *(const uint4*)gbl_row;
        blv[1] = *(const uint4*)(gbl_row + 8);
        uint32_t ro = (uint32_t)(ldr * LDS_H + ldk) * 2;
        *(uint4*)(smem + OFF_ST[0] + OA + ro) = av[0];
        *(uint4*)(smem + OFF_ST[0] + OA + ro + 16) = av[1];
        *(uint4*)(smem + OFF_ST[0] + OBH + ro) = bhv[0];
        *(uint4*)(smem + OFF_ST[0] + OBH + ro + 16) = bhv[1];
        *(uint4*)(smem + OFF_ST[0] + OBL + ro) = blv[0];
        *(uint4*)(smem + OFF_ST[0] + OBL + ro + 16) = blv[1];
    }
    __syncthreads();

    for (int cb = 0; cb < nch; cb++) {
        const int stage = cb & 1;
        if (cb + 1 < nch) {
            const __half* ga = Ap[(cb + 1) >> 2] + (size_t)garow * 128 + ((cb + 1) & 3) * 32 + ldk;
            av[0] = aval ? *(const uint4*)ga : make_uint4(0, 0, 0, 0);
            av[1] = aval ? *(const uint4*)(ga + 8) : make_uint4(0, 0, 0, 0);
            const __half* gh = gbh_row + (cb + 1) * 32;
            const __half* gl = gbl_row + (cb + 1) * 32;
            bhv[0] = *(const uint4*)gh;
            bhv[1] = *(const uint4*)(gh + 8);
            blv[0] = *(const uint4*)gl;
            blv[1] = *(const uint4*)(gl + 8);
        }
        const uint32_t base = sb + OFF_ST[stage];
#pragma unroll
        for (int ks = 0; ks < 32; ks += 16) {
            uint32_t ah[4][4], bh[4][2], bl[4][2];
#pragma unroll
            for (int mi = 0; mi < 4; mi++) {
                uint32_t ra = base + OA + (uint32_t)((a_row + mi * 16) * LDS_H + ks + a_koff) * 2;
                ldm_x4(ah[mi][0], ah[mi][1], ah[mi][2], ah[mi][3], ra);
            }
#pragma unroll
            for (int g = 0; g < 2; g++) {
                uint32_t rb = base + OBH + (uint32_t)((b_row + g * 16) * LDS_H + ks + b_koff) * 2;
                ldm_x4(bh[g * 2][0], bh[g * 2][1], bh[g * 2 + 1][0], bh[g * 2 + 1][1], rb);
                uint32_t rl = base + OBL + (uint32_t)((b_row + g * 16) * LDS_H + ks + b_koff) * 2;
                ldm_x4(bl[g * 2][0], bl[g * 2][1], bl[g * 2 + 1][0], bl[g * 2 + 1][1], rl);
            }
#pragma unroll
            for (int mi = 0; mi < 4; mi++)
#pragma unroll
                for (int nj = 0; nj < 4; nj++) {
                    mma_f16(acc[mi][nj], ah[mi], bh[nj]);
                    mma_f16(acc[mi][nj], ah[mi], bl[nj]);
                }
        }
        if (cb + 1 < nch) {
            uint32_t sbase = OFF_ST[stage ^ 1];
            uint32_t ro = (uint32_t)(ldr * LDS_H + ldk) * 2;
            *(uint4*)(smem + sbase + OA + ro) = av[0];
            *(uint4*)(smem + sbase + OA + ro + 16) = av[1];
            *(uint4*)(smem + sbase + OBH + ro) = bhv[0];
            *(uint4*)(smem + sbase + OBH + ro + 16) = bhv[1];
            *(uint4*)(smem + sbase + OBL + ro) = blv[0];
            *(uint4*)(smem + sbase + OBL + ro + 16) = blv[1];
        }
        __syncthreads();
    }

    // ---- epilogue ----
#pragma unroll
    for (int mi = 0; mi < 4; mi++) {
        int r0 = m0 + wm * 64 + mi * 16 + (lane >> 2);
#pragma unroll
        for (int nj = 0; nj < 4; nj++) {
            int c = wn * 32 + nj * 8 + (lane & 3) * 2;  // 0..126 local
            float b0 = bias_s[c], b1 = bias_s[c + 1];
#pragma unroll
            for (int hh = 0; hh < 2; hh++) {
                int r = r0 + hh * 8;
                if (r >= n) continue;
                float o0 = acc[mi][nj][hh * 2] + b0;
                float o1 = acc[mi][nj][hh * 2 + 1] + b1;
                if (mode == 0) {
                    if (act) { o0 = fmaxf(o0, 0.f); o1 = fmaxf(o1, 0.f); }
                    if (C)  *(float2*)(C + (size_t)r * No + n0 + c) = make_float2(o0, o1);
                    if (Ch) *(__half2*)(Ch + (size_t)r * No + n0 + c) = __floats2half2_rn(o0, o1);
                } else if (mode == 1) {
                    float2 gx = *(const float2*)(Gx + (size_t)r * 384 + n0 + c);
                    float s0 = 1.f / (1.f + expf(-(o0 + gx.x)));
                    float s1 = 1.f / (1.f + expf(-(o1 + gx.y)));
                    if (n0 == 0) {
                        *(float2*)(Z + (size_t)r * 128 + c) = make_float2(s0, s1);
                    } else {
                        float2 hv = *(const float2*)(H + (size_t)r * 128 + c);
                        *(__half2*)(HRh + (size_t)r * 128 + c) =
                            __floats2half2_rn(hv.x * s0, hv.y * s1);
                    }
                } else {
                    float2 gx = *(const float2*)(Gx + (size_t)r * 384 + 256 + c);
                    float ht0 = tanhf(o0 + gx.x);
                    float ht1 = tanhf(o1 + gx.y);
                    float2 zz = *(const float2*)(Z + (size_t)r * 128 + c);
                    float2 hv = *(const float2*)(H + (size_t)r * 128 + c);
                    float h0 = zz.x * hv.x + (1.f - zz.x) * ht0;
                    float h1 = zz.y * hv.y + (1.f - zz.y) * ht1;
                    *(float2*)(H + (size_t)r * 128 + c) = make_float2(h0, h1);
                    *(__half2*)(Hh + (size_t)r * 128 + c) = __floats2half2_rn(h0, h1);
                }
            }
        }
    }
}

// ---------------- weight packing (transposed [No][K], fp16 hi/lo) ----------------
__device__ __forceinline__ void splitw(float v, __half* hi, __half* lo, int i) {
    __half h = __float2half_rn(v);
    hi[i] = h;
    lo[i] = __float2half_rn(v - __half2float(h));
}
__global__ void k_packT(const float* __restrict__ Wxz, const float* __restrict__ Wxr,
                        const float* __restrict__ Wxh, const float* __restrict__ Whz,
                        const float* __restrict__ Whr, const float* __restrict__ Whh,
                        const float* __restrict__ Wd1, const float* __restrict__ Wd2,
                        const float* __restrict__ bxz, const float* __restrict__ bxr,
                        const float* __restrict__ bxh, const float* __restrict__ bhz,
                        const float* __restrict__ bhr,
                        __half* WxHi, __half* WxLo, __half* WhHi, __half* WhLo,
                        __half* WhhHi, __half* WhhLo, __half* Wd1Hi, __half* Wd1Lo,
                        __half* Wd2Hi, __half* Wd2Lo,
                        float* __restrict__ bx, float* __restrict__ bh) {
    int i = blockIdx.x * blockDim.x + threadIdx.x;
    if (i < 384 * 384) {
        int no = i / 384, k = i % 384;
        int kb = k >> 7, fi = k & 127, fo = no & 127;
        const float* W = (no < 128) ? Wxz : (no < 256) ? Wxr : Wxh;
        splitw(W[kb * 16384 + fi * 128 + fo], WxHi, WxLo, i);
    }
    if (i < 256 * 384) {
        int no = i / 384, k = i % 384;
        int kb = k >> 7, fi = k & 127, fo = no & 127;
        const float* W = (no < 128) ? Whz : Whr;
        splitw(W[kb * 16384 + fi * 128 + fo], WhHi, WhLo, i);
    }
    if (i < 128 * 384) {
        int no = i / 384, k = i % 384;
        int kb = k >> 7, fi = k & 127;
        splitw(Whh[kb * 16384 + fi * 128 + no], WhhHi, WhhLo, i);
    }
    if (i < 128 * 128) {
        int no = i / 128, k = i % 128;
        splitw(Wd1[k * 128 + no], Wd1Hi, Wd1Lo, i);
        splitw(Wd2[k * 128 + no], Wd2Hi, Wd2Lo, i);
    }
    if (i < 384) bx[i] = (i < 128) ? bxz[i] : ((i < 256) ? bxr[i - 128] : bxh[i - 256]);
    if (i < 256) bh[i] = (i < 128) ? bhz[i] : bhr[i - 128];
}

// ---------------- driver ----------------
extern "C" void kernel_launch(void* const* d_in, const int* in_sizes, int n_in,
                              void* d_out, int out_size) {
    const float* x   = (const float*)d_in[0];
    const int*   ei  = (const int*)d_in[1];
    const float* Wxz = (const float*)d_in[2];
    const float* Whz = (const float*)d_in[3];
    const float* Wxr = (const float*)d_in[4];
    const float* Whr = (const float*)d_in[5];
    const float* Wxh = (const float*)d_in[6];
    const float* Whh = (const float*)d_in[7];
    const float* bxz = (const float*)d_in[8];
    const float* bhz = (const float*)d_in[9];
    const float* bxr = (const float*)d_in[10];
    const float* bhr = (const float*)d_in[11];
    const float* bxh = (const float*)d_in[12];
    const float* bhh = (const float*)d_in[13];
    const float* Wd1 = (const float*)d_in[14];
    const float* bd1 = (const float*)d_in[15];
    const float* Wd2 = (const float*)d_in[16];
    const float* bd2 = (const float*)d_in[17];
    float* out = (float*)d_out;
    (void)in_sizes; (void)n_in; (void)out_size;

    // side stream + events (created once; creation does not touch device heap)
    static cudaStream_t s1 = nullptr;
    static cudaEvent_t evFork = nullptr, evCsr[TT];
    if (!s1) {
        cudaStreamCreateWithFlags(&s1, cudaStreamNonBlocking);
        cudaEventCreateWithFlags(&evFork, cudaEventDisableTiming);
        for (int t = 0; t < TT; t++) cudaEventCreateWithFlags(&evCsr[t], cudaEventDisableTiming);
    }

    int *p_deg, *p_cnt, *p_bsum, *p_cursor, *p_rowoff4, *p_col4;
    float *p_dinv, *p_w4, *p_H, *p_Gx, *p_Z, *p_bx, *p_bh;
    __half *p_xh, *p_Tx1h, *p_Tx2h, *p_Hh, *p_HRh, *p_D1h;
    __half *p_WxHi, *p_WxLo, *p_WhHi, *p_WhLo, *p_WhhHi, *p_WhhLo;
    __half *p_Wd1Hi, *p_Wd1Lo, *p_Wd2Hi, *p_Wd2Lo;
    cudaGetSymbolAddress((void**)&p_deg, g_deg);
    cudaGetSymbolAddress((void**)&p_cnt, g_cnt);
    cudaGetSymbolAddress((void**)&p_bsum, g_bsum);
    cudaGetSymbolAddress((void**)&p_cursor, g_cursor);
    cudaGetSymbolAddress((void**)&p_rowoff4, g_rowoff4);
    cudaGetSymbolAddress((void**)&p_col4, g_col4);
    cudaGetSymbolAddress((void**)&p_w4, g_w4);
    cudaGetSymbolAddress((void**)&p_dinv, g_dinv);
    cudaGetSymbolAddress((void**)&p_xh, g_xh);
    cudaGetSymbolAddress((void**)&p_Tx1h, g_Tx1h);
    cudaGetSymbolAddress((void**)&p_Tx2h, g_Tx2h);
    cudaGetSymbolAddress((void**)&p_H, g_H);
    cudaGetSymbolAddress((void**)&p_Hh, g_Hh);
    cudaGetSymbolAddress((void**)&p_HRh, g_HRh);
    cudaGetSymbolAddress((void**)&p_D1h, g_D1h);
    cudaGetSymbolAddress((void**)&p_Gx, g_Gx);
    cudaGetSymbolAddress((void**)&p_Z, g_Z);
    cudaGetSymbolAddress((void**)&p_WxHi, g_WxHi);
    cudaGetSymbolAddress((void**)&p_WxLo, g_WxLo);
    cudaGetSymbolAddress((void**)&p_WhHi, g_WhHi);
    cudaGetSymbolAddress((void**)&p_WhLo, g_WhLo);
    cudaGetSymbolAddress((void**)&p_WhhHi, g_WhhHi);
    cudaGetSymbolAddress((void**)&p_WhhLo, g_WhhLo);
    cudaGetSymbolAddress((void**)&p_Wd1Hi, g_Wd1Hi);
    cudaGetSymbolAddress((void**)&p_Wd1Lo, g_Wd1Lo);
    cudaGetSymbolAddress((void**)&p_Wd2Hi, g_Wd2Hi);
    cudaGetSymbolAddress((void**)&p_Wd2Lo, g_Wd2Lo);
    cudaGetSymbolAddress((void**)&p_bx, g_bx);
    cudaGetSymbolAddress((void**)&p_bh, g_bh);

    cudaFuncSetAttribute(k_gemm_h, cudaFuncAttributeMaxDynamicSharedMemorySize,
                         GEMM_SMEM_BYTES);

    const int threads = 256;
    const int gE = (EE + threads - 1) / threads;
    const int gN = (NN + threads - 1) / threads;
    dim3 spmmBlk(64, 4);
    int spmmGrid = (NN + 3) / 4;
    const int MB = (NN + 127) / 128;

    // ---- fork side stream ----
    cudaEventRecord(evFork, 0);
    cudaStreamWaitEvent(s1, evFork, 0);

    // side stream: weight pack, x cast, all 4 CSR builds
    k_packT<<<(384 * 384 + threads - 1) / threads, threads, 0, s1>>>(
        Wxz, Wxr, Wxh, Whz, Whr, Whh, Wd1, Wd2, bxz, bxr, bxh, bhz, bhr,
        p_WxHi, p_WxLo, p_WhHi, p_WhLo, p_WhhHi, p_WhhLo,
        p_Wd1Hi, p_Wd1Lo, p_Wd2Hi, p_Wd2Lo, p_bx, p_bh);
    {
        int n4 = TT * NN * FF / 4;
        k_cast<<<(n4 + threads - 1) / threads, threads, 0, s1>>>(
            (const float4*)x, (__half2*)p_xh, n4);
    }
    for (int t = 0; t < TT; t++) {
        const int* src = ei + (size_t)t * 2 * EE;
        const int* dst = src + EE;
        int*   ro = p_rowoff4 + (size_t)t * (NN + 1);
        int*   cl = p_col4 + (size_t)t * EE;
        float* wt = p_w4 + (size_t)t * EE;
        cudaMemsetAsync(p_deg, 0, NN * sizeof(int), s1);
        cudaMemsetAsync(p_cnt, 0, NN * sizeof(int), s1);
        k_hist<<<gE, threads, 0, s1>>>(src, dst, p_deg, p_cnt, EE);
        k_dinv<<<gN, threads, 0, s1>>>(p_deg, p_dinv, NN);
        k_scan_part<<<NB, SCAN_B, 0, s1>>>(p_cnt, p_bsum, NN);
        k_scan_top<<<1, SCAN_B, 0, s1>>>(p_bsum, NB, ro, NN);
        k_scan_down<<<NB, SCAN_B, 0, s1>>>(p_cnt, p_bsum, ro, NN);
        cudaMemcpyAsync(p_cursor, ro, NN * sizeof(int), cudaMemcpyDeviceToDevice, s1);
        k_scatter<<<gE, threads, 0, s1>>>(src, dst, p_dinv, p_cursor, cl, wt, EE);
        cudaEventRecord(evCsr[t], s1);
    }

    // main stream: init H
    cudaMemsetAsync(p_H, 0, (size_t)NN * FF * sizeof(float));
    cudaMemsetAsync(p_Hh, 0, (size_t)NN * FF * sizeof(__half));

    for (int t = 0; t < TT; t++) {
        const __half* xth = p_xh + (size_t)t * NN * FF;
        const int*   ro = p_rowoff4 + (size_t)t * (NN + 1);
        const int*   cl = p_col4 + (size_t)t * EE;
        const float* wt = p_w4 + (size_t)t * EE;
        cudaStreamWaitEvent(0, evCsr[t], 0);

        // x path -> Gx (mode 0)
        k_spmm_h<<<spmmGrid, spmmBlk>>>(ro, cl, wt, (const __half2*)xth,
                                        nullptr, (__half2*)p_Tx1h, NN);
        k_spmm_h<<<spmmGrid, spmmBlk>>>(ro, cl, wt, (const __half2*)p_Tx1h,
                                        (const __half2*)xth, (__half2*)p_Tx2h, NN);
        k_gemm_h<<<dim3(MB, 3), 256, GEMM_SMEM_BYTES>>>(
            xth, p_Tx1h, p_Tx2h, 3, p_WxHi, p_WxLo, 384, p_bx, 0, 0,
            p_Gx, nullptr, nullptr, nullptr, nullptr, nullptr, nullptr, NN, 384);
        // H path -> fused gates1 (mode 1): Z + HRh
        k_spmm_h<<<spmmGrid, spmmBlk>>>(ro, cl, wt, (const __half2*)p_Hh,
                                        nullptr, (__half2*)p_Tx1h, NN);
        k_spmm_h<<<spmmGrid, spmmBlk>>>(ro, cl, wt, (const __half2*)p_Tx1h,
                                        (const __half2*)p_Hh, (__half2*)p_Tx2h, NN);
        k_gemm_h<<<dim3(MB, 2), 256, GEMM_SMEM_BYTES>>>(
            p_Hh, p_Tx1h, p_Tx2h, 3, p_WhHi, p_WhLo, 384, p_bh, 1, 0,
            nullptr, nullptr, p_Gx, p_H, p_Z, p_HRh, nullptr, NN, 256);
        // HR path -> fused gates2 (mode 2): H, Hh
        k_spmm_h<<<spmmGrid, spmmBlk>>>(ro, cl, wt, (const __half2*)p_HRh,
                                        nullptr, (__half2*)p_Tx1h, NN);
        k_spmm_h<<<spmmGrid, spmmBlk>>>(ro, cl, wt, (const __half2*)p_Tx1h,
                                        (const __half2*)p_HRh, (__half2*)p_Tx2h, NN);
        k_gemm_h<<<dim3(MB, 1), 256, GEMM_SMEM_BYTES>>>(
            p_HRh, p_Tx1h, p_Tx2h, 3, p_WhhHi, p_WhhLo, 384, bhh, 2, 0,
            nullptr, nullptr, p_Gx, p_H, p_Z, nullptr, p_Hh, NN, 128);
    }

    // decoder
    k_gemm_h<<<dim3(MB, 1), 256, GEMM_SMEM_BYTES>>>(
        p_Hh, nullptr, nullptr, 1, p_Wd1Hi, p_Wd1Lo, 128, bd1, 0, 1,
        nullptr, p_D1h, nullptr, nullptr, nullptr, nullptr, nullptr, NN, 128);
    k_gemm_h<<<dim3(MB, 1), 256, GEMM_SMEM_BYTES>>>(
        p_D1h, nullptr, nullptr, 1, p_Wd2Hi, p_Wd2Lo, 128, bd2, 0, 0,
        out, nullptr, nullptr, nullptr, nullptr, nullptr, nullptr, NN, 128);
    cudaMemcpyAsync(out + (size_t)NN * FF, p_H, (size_t)NN * FF * sizeof(float),
                    cudaMemcpyDeviceToDevice);
}